// round 3
// baseline (speedup 1.0000x reference)
#include <cuda_runtime.h>
#include <cstdint>

// DocREDModel: fused entity-pool -> tanh-projection -> block-bilinear classifier
// B=16 S=2048 H=768 E=32 M=4 P=128 L=97 BLOCK=64
//
// Stage split:
//  k1: ent[be][h]  (512 x 768)  dedup-weighted gather-sum
//  k2: zh = tanh(ent@Wh+bh), zt = tanh(ent@Wt+bt)   (per-ENTITY: 512 rows, 4x fewer
//      FLOPs than per-pair)
//  k3: out = bc broadcast
//  k4: out[n][l] += sum_k A[n][k]*Wc[k][l],  A generated on the fly from
//      b1[n,cb,i]*b2[n,cb,j].  Packed f32x2 FMA (sm_103a scalar FFMA is half-rate).

#define B_    16
#define S_    2048
#define H_    768
#define E_    32
#define P_    128
#define L_    97
#define NROWS 2048     // B*P
#define NENT  512      // B*E

__device__ float g_ent[NENT * H_];
__device__ float g_zh[NENT * H_];
__device__ float g_zt[NENT * H_];

// ---------------------------------------------------------------- kernel 1
__global__ void build_ent_kernel(const float* __restrict__ feats,
                                 const int* __restrict__ pos) {
    int be = blockIdx.x;           // 0..511
    int b  = be >> 5;
    const int* pp = pos + be * 4;
    int p0 = pp[0], p1 = pp[1], p2 = pp[2], p3 = pp[3];
    float w1 = (p1 != p0) ? 1.f : 0.f;
    float w2 = (p2 != p0 && p2 != p1) ? 1.f : 0.f;
    float w3 = (p3 != p0 && p3 != p1 && p3 != p2) ? 1.f : 0.f;
    const float* base = feats + (size_t)b * S_ * H_;
    const float4* r0 = (const float4*)(base + (size_t)p0 * H_);
    const float4* r1 = (const float4*)(base + (size_t)p1 * H_);
    const float4* r2 = (const float4*)(base + (size_t)p2 * H_);
    const float4* r3 = (const float4*)(base + (size_t)p3 * H_);
    int t = threadIdx.x;           // 0..191, 192*4 = 768
    float4 v0 = r0[t], v1 = r1[t], v2 = r2[t], v3 = r3[t];
    float4 o;
    o.x = v0.x + w1 * v1.x + w2 * v2.x + w3 * v3.x;
    o.y = v0.y + w1 * v1.y + w2 * v2.y + w3 * v3.y;
    o.z = v0.z + w1 * v1.z + w2 * v2.z + w3 * v3.z;
    o.w = v0.w + w1 * v1.w + w2 * v2.w + w3 * v3.w;
    ((float4*)(g_ent + (size_t)be * H_))[t] = o;
}

// ---------------------------------------------------------------- kernel 2
// Z = tanh(ENT @ W + b), 512x768x768.  blockIdx.z: 0 -> (Wh,bh,zh), 1 -> (Wt,bt,zt)
__global__ void gemm_tanh_kernel(const float* __restrict__ Wh,
                                 const float* __restrict__ bh,
                                 const float* __restrict__ Wt,
                                 const float* __restrict__ bt) {
    const float* W    = blockIdx.z ? Wt : Wh;
    const float* bias = blockIdx.z ? bt : bh;
    float*       Z    = blockIdx.z ? g_zt : g_zh;

    __shared__ float As[16][68];   // A transposed: [k][m]
    __shared__ float Bs[16][68];   // [k][n]

    int tid = threadIdx.x;         // 128 threads
    int mg = tid & 15;             // m-group (4 rows)
    int ng = tid >> 4;             // n-group (8 cols)
    int m0 = blockIdx.x * 64;
    int n0 = blockIdx.y * 64;

    float acc[4][8];
#pragma unroll
    for (int i = 0; i < 4; i++)
#pragma unroll
        for (int j = 0; j < 8; j++) acc[i][j] = 0.f;

    for (int k0 = 0; k0 < H_; k0 += 16) {
#pragma unroll
        for (int e = tid; e < 1024; e += 128) {
            int m = e >> 4, kk = e & 15;
            As[kk][m] = g_ent[(m0 + m) * H_ + k0 + kk];
        }
#pragma unroll
        for (int e = tid; e < 1024; e += 128) {
            int kk = e >> 6, nn = e & 63;
            Bs[kk][nn] = W[(k0 + kk) * H_ + n0 + nn];
        }
        __syncthreads();
#pragma unroll
        for (int kk = 0; kk < 16; kk++) {
            float4 a  = *(const float4*)&As[kk][mg * 4];
            float4 c0 = *(const float4*)&Bs[kk][ng * 8];
            float4 c1 = *(const float4*)&Bs[kk][ng * 8 + 4];
            float av[4] = {a.x, a.y, a.z, a.w};
            float bv[8] = {c0.x, c0.y, c0.z, c0.w, c1.x, c1.y, c1.z, c1.w};
#pragma unroll
            for (int i = 0; i < 4; i++)
#pragma unroll
                for (int j = 0; j < 8; j++) acc[i][j] += av[i] * bv[j];
        }
        __syncthreads();
    }
#pragma unroll
    for (int i = 0; i < 4; i++) {
        int r = m0 + mg * 4 + i;
#pragma unroll
        for (int j = 0; j < 8; j++) {
            int c = n0 + ng * 8 + j;
            Z[r * H_ + c] = tanhf(acc[i][j] + bias[c]);
        }
    }
}

// ---------------------------------------------------------------- kernel 3
__global__ void init_out_kernel(const float* __restrict__ bc, float* __restrict__ out) {
    int i = blockIdx.x * blockDim.x + threadIdx.x;
    if (i < NROWS * L_) out[i] = bc[i % L_];
}

// ---------------------------------------------------------------- kernel 4
// Bilinear GEMM: out[n][l] += sum_{k in split} A[n][k] * Wc[k][l]
//   A[n][cb*4096 + i*64 + j] = b1[n][cb*64+i] * b2[n][cb*64+j]
// Grid: (32 m-tiles of 64 rows, 24 K-splits = half-cb of 2048 k each)
// 224 threads: lgroup = tid%14 (8 l each, 112 padded cols), ngroup = tid/14 (4 n each,
// held as 2 f32x2 pairs).  fp32 accumulation via packed fma.rn.f32x2.

__device__ __forceinline__ unsigned long long ffma2(unsigned long long a,
                                                    unsigned long long b,
                                                    unsigned long long c) {
    unsigned long long d;
    asm("fma.rn.f32x2 %0, %1, %2, %3;" : "=l"(d) : "l"(a), "l"(b), "l"(c));
    return d;
}
__device__ __forceinline__ unsigned long long fmul2(unsigned long long a,
                                                    unsigned long long b) {
    unsigned long long d;
    asm("mul.rn.f32x2 %0, %1, %2;" : "=l"(d) : "l"(a), "l"(b));
    return d;
}
__device__ __forceinline__ unsigned long long fsplat(float x) {
    unsigned long long d;
    asm("mov.b64 %0, {%1, %1};" : "=l"(d) : "f"(x));
    return d;
}

#define ROWN 68     // padded n-row stride for b1T/b2T
#define WROW 112    // padded Wc tile row (97 real + 15 zero)
// dynamic smem: b1T 32*68 + b2T 64*68 + Ws 64*112 floats + 128 ints
#define K4_SMEM_FLOATS (32 * ROWN + 64 * ROWN + 64 * WROW)
#define K4_SMEM_BYTES  (K4_SMEM_FLOATS * 4 + 128 * 4)

__global__ void __launch_bounds__(224, 3)
bilinear_kernel(const int* __restrict__ ht, const float* __restrict__ Wc,
                float* __restrict__ out) {
    extern __shared__ float sm[];
    float* b1T = sm;                             // [ii][n]  32 x 68
    float* b2T = sm + 32 * ROWN;                 // [j][n]   64 x 68
    float* Ws  = sm + 32 * ROWN + 64 * ROWN;     // [j][l]   64 x 112
    int*   rh  = (int*)(sm + K4_SMEM_FLOATS);
    int*   rt  = rh + 64;

    int tid   = threadIdx.x;                     // 0..223
    int m0    = blockIdx.x * 64;                 // n-tile base
    int s     = blockIdx.y;                      // k-split 0..23
    int cb    = s >> 1;
    int ihalf = s & 1;
    int colb1 = cb * 64 + ihalf * 32;            // b1 col base (32 cols)
    int colb2 = cb * 64;                         // b2 col base (64 cols)

    if (tid < 64) {
        int ng = m0 + tid;
        int b  = ng >> 7;                        // ng = b*128 + p
        rh[tid] = b * E_ + ht[2 * ng];
        rt[tid] = b * E_ + ht[2 * ng + 1];
    }
    __syncthreads();

    // gather b1 (transposed [i][n]) and b2 (transposed [j][n])
    for (int e = tid; e < 32 * 64; e += 224) {
        int n = e >> 5, ii = e & 31;
        b1T[ii * ROWN + n] = g_zh[rh[n] * H_ + colb1 + ii];
    }
    for (int e = tid; e < 64 * 64; e += 224) {
        int n = e >> 6, j = e & 63;
        b2T[j * ROWN + n] = g_zt[rt[n] * H_ + colb2 + j];
    }

    int lg   = tid % 14;
    int ngp  = tid / 14;                          // 0..15
    int nloc = ngp * 4;
    int l0   = lg * 8;

    unsigned long long acc[2][8];
#pragma unroll
    for (int a = 0; a < 2; a++)
#pragma unroll
        for (int c = 0; c < 8; c++) acc[a][c] = 0ull;

    for (int ii = 0; ii < 32; ii++) {
        __syncthreads();  // (ii=0: b1T/b2T ready; ii>0: prior inner done before Ws rewrite)
        int k0 = (colb1 + ii) * 64;               // global Wc row base for this chunk
        for (int e = tid; e < 64 * 112; e += 224) {
            int j = e / 112, l = e - j * 112;
            Ws[j * WROW + l] = (l < L_) ? Wc[(size_t)(k0 + j) * L_ + l] : 0.f;
        }
        __syncthreads();

        ulonglong2 b1p = *(const ulonglong2*)&b1T[ii * ROWN + nloc];  // (n0,n1),(n2,n3)

#pragma unroll 4
        for (int j = 0; j < 64; j++) {
            ulonglong2 q = *(const ulonglong2*)&b2T[j * ROWN + nloc];
            unsigned long long a0 = fmul2(q.x, b1p.x);   // A pairs = b1*b2
            unsigned long long a1 = fmul2(q.y, b1p.y);
            float4 w0 = *(const float4*)&Ws[j * WROW + l0];
            float4 w1 = *(const float4*)&Ws[j * WROW + l0 + 4];
            float wv[8] = {w0.x, w0.y, w0.z, w0.w, w1.x, w1.y, w1.z, w1.w};
#pragma unroll
            for (int c = 0; c < 8; c++) {
                unsigned long long wp = fsplat(wv[c]);   // ALU-pipe splat
                acc[0][c] = ffma2(a0, wp, acc[0][c]);
                acc[1][c] = ffma2(a1, wp, acc[1][c]);
            }
        }
    }

#pragma unroll
    for (int a = 0; a < 2; a++) {
        int nrow0 = m0 + nloc + a * 2;
#pragma unroll
        for (int c = 0; c < 8; c++) {
            int l = l0 + c;
            if (l < L_) {
                float lo = __uint_as_float((unsigned int)(acc[a][c] & 0xffffffffull));
                float hi = __uint_as_float((unsigned int)(acc[a][c] >> 32));
                atomicAdd(&out[nrow0 * L_ + l], lo);
                atomicAdd(&out[(nrow0 + 1) * L_ + l], hi);
            }
        }
    }
}

// ---------------------------------------------------------------- launch
extern "C" void kernel_launch(void* const* d_in, const int* in_sizes, int n_in,
                              void* d_out, int out_size) {
    const float* feats = (const float*)d_in[0];   // (16,2048,768) f32
    const int*   pos   = (const int*)d_in[1];     // (16,32,4)
    const int*   ht    = (const int*)d_in[2];     // (16,128,2)
    const float* Wh    = (const float*)d_in[3];   // (768,768)
    const float* bh    = (const float*)d_in[4];   // (768,)
    const float* Wt    = (const float*)d_in[5];   // (768,768)
    const float* bt    = (const float*)d_in[6];   // (768,)
    const float* Wc    = (const float*)d_in[7];   // (49152,97)
    const float* bc    = (const float*)d_in[8];   // (97,)
    float*       out   = (float*)d_out;           // (2048,97)

    cudaFuncSetAttribute(bilinear_kernel,
                         cudaFuncAttributeMaxDynamicSharedMemorySize, K4_SMEM_BYTES);

    build_ent_kernel<<<NENT, 192>>>(feats, pos);

    dim3 g2(NENT / 64, H_ / 64, 2);
    gemm_tanh_kernel<<<g2, 128>>>(Wh, bh, Wt, bt);

    init_out_kernel<<<(NROWS * L_ + 255) / 256, 256>>>(bc, out);

    dim3 g4(NROWS / 64, 24);
    bilinear_kernel<<<g4, 224, K4_SMEM_BYTES>>>(ht, Wc, out);
}

// round 4
// speedup vs baseline: 1.4828x; 1.4828x over previous
#include <cuda_runtime.h>
#include <cstdint>

// DocREDModel: entity-pool -> tanh-projection -> block-bilinear classifier
// B=16 S=2048 H=768 E=32 M=4 P=128 L=97 BLOCK=64
//
//  k1: ent (512x768) dedup-weighted gather-sum
//  k2: zh = tanh(ent@Wh+bh), zt = tanh(ent@Wt+bt)  (per-entity, packed f32x2, dup-B)
//  k3: out = bc broadcast (+ work-queue reset)
//  k4: l=96 column GEMV (so main GEMM uses exactly 96 cols = 12 warps x 8, no pad)
//  k5: persistent bilinear GEMM, tile 128n x 96l, atomic work queue,
//      warp-uniform l-blocks (broadcast Ws), pre-duplicated f32x2 weights.

#define B_    16
#define S_    2048
#define H_    768
#define E_    32
#define L_    97
#define NROWS 2048     // B*P
#define NENT  512      // B*E

typedef unsigned long long ull;

__device__ float g_ent[NENT * H_];
__device__ float g_zh[NENT * H_];
__device__ float g_zt[NENT * H_];
__device__ int   g_qhead;

__device__ __forceinline__ ull ffma2(ull a, ull b, ull c) {
    ull d; asm("fma.rn.f32x2 %0, %1, %2, %3;" : "=l"(d) : "l"(a), "l"(b), "l"(c));
    return d;
}
__device__ __forceinline__ ull fmul2(ull a, ull b) {
    ull d; asm("mul.rn.f32x2 %0, %1, %2;" : "=l"(d) : "l"(a), "l"(b));
    return d;
}
__device__ __forceinline__ float lo32(ull v) { return __uint_as_float((unsigned)(v & 0xffffffffull)); }
__device__ __forceinline__ float hi32(ull v) { return __uint_as_float((unsigned)(v >> 32)); }

// ---------------------------------------------------------------- kernel 1
__global__ void build_ent_kernel(const float* __restrict__ feats,
                                 const int* __restrict__ pos) {
    int be = blockIdx.x;
    int b  = be >> 5;
    const int* pp = pos + be * 4;
    int p0 = pp[0], p1 = pp[1], p2 = pp[2], p3 = pp[3];
    float w1 = (p1 != p0) ? 1.f : 0.f;
    float w2 = (p2 != p0 && p2 != p1) ? 1.f : 0.f;
    float w3 = (p3 != p0 && p3 != p1 && p3 != p2) ? 1.f : 0.f;
    const float* base = feats + (size_t)b * S_ * H_;
    const float4* r0 = (const float4*)(base + (size_t)p0 * H_);
    const float4* r1 = (const float4*)(base + (size_t)p1 * H_);
    const float4* r2 = (const float4*)(base + (size_t)p2 * H_);
    const float4* r3 = (const float4*)(base + (size_t)p3 * H_);
    int t = threadIdx.x;   // 192 threads * float4 = 768
    float4 v0 = r0[t], v1 = r1[t], v2 = r2[t], v3 = r3[t];
    float4 o;
    o.x = v0.x + w1 * v1.x + w2 * v2.x + w3 * v3.x;
    o.y = v0.y + w1 * v1.y + w2 * v2.y + w3 * v3.y;
    o.z = v0.z + w1 * v1.z + w2 * v2.z + w3 * v3.z;
    o.w = v0.w + w1 * v1.w + w2 * v2.w + w3 * v3.w;
    ((float4*)(g_ent + (size_t)be * H_))[t] = o;
}

// ---------------------------------------------------------------- kernel 2
// Z = tanh(ENT @ W + b), 512x768x768.  Tile 64m x 128n, 256 thr (16 mg x 16 ng),
// packed f32x2 along m, B duplicated as (w,w) pairs in smem (no splat MOVs).
__global__ void __launch_bounds__(256)
gemm_tanh_kernel(const float* __restrict__ Wh, const float* __restrict__ bh,
                 const float* __restrict__ Wt, const float* __restrict__ bt) {
    const float* W    = blockIdx.z ? Wt : Wh;
    const float* bias = blockIdx.z ? bt : bh;
    float*       Z    = blockIdx.z ? g_zt : g_zh;

    __shared__ float AsT[16 * 68];    // [k][m], stride 68
    __shared__ float Bd[16 * 256];    // [k][128 dup-pairs], stride 256 floats

    int tid = threadIdx.x;
    int mg  = tid & 15;               // 4 m each (2 pairs)
    int ng  = tid >> 4;               // 8 n each
    int m0  = blockIdx.x * 64;
    int n0  = blockIdx.y * 128;

    ull acc[2][8];
#pragma unroll
    for (int p = 0; p < 2; p++)
#pragma unroll
        for (int c = 0; c < 8; c++) acc[p][c] = 0ull;

    for (int k0 = 0; k0 < H_; k0 += 16) {
        __syncthreads();
#pragma unroll
        for (int e = tid; e < 1024; e += 256) {
            int kk = e & 15, m = e >> 4;
            AsT[kk * 68 + m] = g_ent[(m0 + m) * H_ + k0 + kk];
        }
#pragma unroll
        for (int e = tid; e < 2048; e += 256) {
            int n = e & 127, kk = e >> 7;
            float w = W[(k0 + kk) * H_ + n0 + n];
            ((float2*)Bd)[kk * 128 + n] = make_float2(w, w);
        }
        __syncthreads();
#pragma unroll
        for (int kk = 0; kk < 16; kk++) {
            ulonglong2 av = *(const ulonglong2*)&AsT[kk * 68 + mg * 4];
            const ulonglong2* wp = (const ulonglong2*)&Bd[kk * 256 + ng * 16];
            ulonglong2 w01 = wp[0], w23 = wp[1], w45 = wp[2], w67 = wp[3];
            ull w[8] = {w01.x, w01.y, w23.x, w23.y, w45.x, w45.y, w67.x, w67.y};
#pragma unroll
            for (int c = 0; c < 8; c++) {
                acc[0][c] = ffma2(av.x, w[c], acc[0][c]);
                acc[1][c] = ffma2(av.y, w[c], acc[1][c]);
            }
        }
    }
#pragma unroll
    for (int p = 0; p < 2; p++) {
#pragma unroll
        for (int c = 0; c < 8; c++) {
            int n = n0 + ng * 8 + c;
            float bv = bias[n];
            int m = m0 + mg * 4 + 2 * p;
            Z[m * H_ + n]       = tanhf(lo32(acc[p][c]) + bv);
            Z[(m + 1) * H_ + n] = tanhf(hi32(acc[p][c]) + bv);
        }
    }
}

// ---------------------------------------------------------------- kernel 3
__global__ void init_out_kernel(const float* __restrict__ bc, float* __restrict__ out) {
    int i = blockIdx.x * blockDim.x + threadIdx.x;
    if (i == 0) g_qhead = 0;
    if (i < NROWS * L_) out[i] = bc[i % L_];
}

// ---------------------------------------------------------------- kernel 4
// 97th logit column: out[n][96] += sum_k b1[n,i(k)] * b2[n,j(k)] * Wc[k][96]
// 128 blocks (16 n each), 128 threads (4 n-groups x 32 k-slices).
__global__ void __launch_bounds__(128)
l96_kernel(const int* __restrict__ ht, const float* __restrict__ Wc,
           float* __restrict__ out) {
    __shared__ float b1c[64 * 16];
    __shared__ float b2c[64 * 16];
    __shared__ float w96s[4096];
    __shared__ int rh[16], rt[16];

    int tid = threadIdx.x;
    int nb  = blockIdx.x * 16;
    if (tid < 16) {
        int g = nb + tid;
        int b = g >> 7;
        rh[tid] = b * E_ + ht[2 * g];
        rt[tid] = b * E_ + ht[2 * g + 1];
    }
    __syncthreads();

    int ng = tid & 3;    // 4 n (2 pairs)
    int ks = tid >> 2;   // 32 slices of 128 k
    ull acc0 = 0, acc1 = 0;

    for (int cb = 0; cb < 12; cb++) {
        __syncthreads();
        for (int e = tid; e < 1024; e += 128) {
            int i = e & 63, n = e >> 6;
            b1c[i * 16 + n] = g_zh[rh[n] * H_ + cb * 64 + i];
            b2c[i * 16 + n] = g_zt[rt[n] * H_ + cb * 64 + i];
        }
        for (int e = tid; e < 4096; e += 128)
            w96s[e] = Wc[(size_t)(cb * 4096 + e) * L_ + 96];
        __syncthreads();

        int base = ks * 128;
#pragma unroll 4
        for (int r = 0; r < 128; r++) {
            int kl = base + r;
            int i = kl >> 6, j = kl & 63;
            ulonglong2 q1 = *(const ulonglong2*)&b1c[i * 16 + ng * 4];
            ulonglong2 q2 = *(const ulonglong2*)&b2c[j * 16 + ng * 4];
            float wv = w96s[kl];
            ull wp; asm("mov.b64 %0, {%1, %1};" : "=l"(wp) : "f"(wv));
            acc0 = ffma2(fmul2(q1.x, q2.x), wp, acc0);
            acc1 = ffma2(fmul2(q1.y, q2.y), wp, acc1);
        }
    }
    int n0 = nb + ng * 4;
    atomicAdd(&out[(n0 + 0) * L_ + 96], lo32(acc0));
    atomicAdd(&out[(n0 + 1) * L_ + 96], hi32(acc0));
    atomicAdd(&out[(n0 + 2) * L_ + 96], lo32(acc1));
    atomicAdd(&out[(n0 + 3) * L_ + 96], hi32(acc1));
}

// ---------------------------------------------------------------- kernel 5
// Persistent bilinear GEMM, l = 0..95.
// Items: 384 = 16 n-tiles (128 rows) x 24 k-splits (cb 0..11 x ihalf).
// Block 384 thr = 12 warps; warp w covers l-block [8w, 8w+8); lanes cover n
// (4 rows each as 2 f32x2 pairs).  Per item per ii: Ws = 64 Wc rows stored as
// duplicated (w,w) pairs -> inner-loop Ws loads are pure warp broadcasts.

#define NSTRIDE 132                       // padded n-stride (16B-aligned rows)
#define K5_B1_F   (32 * NSTRIDE)          // 4224 floats
#define K5_B2_F   (64 * NSTRIDE)          // 8448 floats
#define K5_WS_F   (64 * 96 * 2)           // 12288 floats (dup pairs)
#define K5_FLOATS (K5_B1_F + K5_B2_F + K5_WS_F)
#define K5_SMEM_BYTES (K5_FLOATS * 4 + 257 * 4)
#define N_ITEMS 384

__global__ void __launch_bounds__(384, 2)
bilinear_kernel(const int* __restrict__ ht, const float* __restrict__ Wc,
                float* __restrict__ out) {
    extern __shared__ float sm[];
    float* b1T = sm;                       // [i 0..31][n 0..127] stride 132
    float* b2T = sm + K5_B1_F;             // [j 0..63][n]        stride 132
    float* Wsd = sm + K5_B1_F + K5_B2_F;   // [j 0..63][96 pairs] stride 192 fl
    int*   rh  = (int*)(sm + K5_FLOATS);
    int*   rt  = rh + 128;
    int*   s_item = rt + 128;

    int tid  = threadIdx.x;
    int warp = tid >> 5;
    int lane = tid & 31;
    int nloc = lane * 4;
    int lq   = warp * 16;                  // float offset into dup-pair row
    int lfill = tid % 96;
    int j0    = tid / 96;

    for (;;) {
        __syncthreads();
        if (tid == 0) *s_item = atomicAdd(&g_qhead, 1);
        __syncthreads();
        int item = *s_item;
        if (item >= N_ITEMS) break;

        int nt    = item & 15;
        int ks    = item >> 4;
        int cb    = ks >> 1;
        int ihalf = ks & 1;
        int colb1 = cb * 64 + ihalf * 32;
        int colb2 = cb * 64;
        int ntbase = nt * 128;

        if (tid < 128) {
            int g = ntbase + tid;
            rh[tid] = nt * E_ + ht[2 * g];
            rt[tid] = nt * E_ + ht[2 * g + 1];
        }
        __syncthreads();

        for (int e = tid; e < 32 * 128; e += 384) {
            int i = e & 31, n = e >> 5;
            b1T[i * NSTRIDE + n] = g_zh[rh[n] * H_ + colb1 + i];
        }
        for (int e = tid; e < 64 * 128; e += 384) {
            int j = e & 63, n = e >> 6;
            b2T[j * NSTRIDE + n] = g_zt[rt[n] * H_ + colb2 + j];
        }

        ull acc[2][8];
#pragma unroll
        for (int p = 0; p < 2; p++)
#pragma unroll
            for (int c = 0; c < 8; c++) acc[p][c] = 0ull;

        for (int ii = 0; ii < 32; ii++) {
            __syncthreads();               // prior inner reads done (covers fills @ii=0)
            {
                int k0 = (colb1 + ii) * 64;
                const float* wc = Wc + (size_t)k0 * L_ + lfill;
#pragma unroll
                for (int s = 0; s < 16; s++) {
                    int j = j0 + s * 4;
                    float w = wc[(size_t)j * L_];
                    ((float2*)Wsd)[j * 96 + lfill] = make_float2(w, w);
                }
            }
            __syncthreads();

            ulonglong2 b1p = *(const ulonglong2*)(b1T + ii * NSTRIDE + nloc);

#pragma unroll 4
            for (int j = 0; j < 64; j++) {
                ulonglong2 q = *(const ulonglong2*)(b2T + j * NSTRIDE + nloc);
                ull a0 = fmul2(q.x, b1p.x);
                ull a1 = fmul2(q.y, b1p.y);
                const ulonglong2* wp = (const ulonglong2*)(Wsd + j * 192 + lq);
                ulonglong2 w01 = wp[0], w23 = wp[1], w45 = wp[2], w67 = wp[3];
                acc[0][0] = ffma2(a0, w01.x, acc[0][0]);
                acc[1][0] = ffma2(a1, w01.x, acc[1][0]);
                acc[0][1] = ffma2(a0, w01.y, acc[0][1]);
                acc[1][1] = ffma2(a1, w01.y, acc[1][1]);
                acc[0][2] = ffma2(a0, w23.x, acc[0][2]);
                acc[1][2] = ffma2(a1, w23.x, acc[1][2]);
                acc[0][3] = ffma2(a0, w23.y, acc[0][3]);
                acc[1][3] = ffma2(a1, w23.y, acc[1][3]);
                acc[0][4] = ffma2(a0, w45.x, acc[0][4]);
                acc[1][4] = ffma2(a1, w45.x, acc[1][4]);
                acc[0][5] = ffma2(a0, w45.y, acc[0][5]);
                acc[1][5] = ffma2(a1, w45.y, acc[1][5]);
                acc[0][6] = ffma2(a0, w67.x, acc[0][6]);
                acc[1][6] = ffma2(a1, w67.x, acc[1][6]);
                acc[0][7] = ffma2(a0, w67.y, acc[0][7]);
                acc[1][7] = ffma2(a1, w67.y, acc[1][7]);
            }
        }

        int l0  = warp * 8;
        int nb0 = ntbase + nloc;
#pragma unroll
        for (int c = 0; c < 8; c++) {
            int l = l0 + c;
            atomicAdd(&out[(nb0 + 0) * L_ + l], lo32(acc[0][c]));
            atomicAdd(&out[(nb0 + 1) * L_ + l], hi32(acc[0][c]));
            atomicAdd(&out[(nb0 + 2) * L_ + l], lo32(acc[1][c]));
            atomicAdd(&out[(nb0 + 3) * L_ + l], hi32(acc[1][c]));
        }
    }
}

// ---------------------------------------------------------------- launch
extern "C" void kernel_launch(void* const* d_in, const int* in_sizes, int n_in,
                              void* d_out, int out_size) {
    const float* feats = (const float*)d_in[0];   // (16,2048,768)
    const int*   pos   = (const int*)d_in[1];     // (16,32,4)
    const int*   ht    = (const int*)d_in[2];     // (16,128,2)
    const float* Wh    = (const float*)d_in[3];
    const float* bh    = (const float*)d_in[4];
    const float* Wt    = (const float*)d_in[5];
    const float* bt    = (const float*)d_in[6];
    const float* Wc    = (const float*)d_in[7];   // (49152,97)
    const float* bc    = (const float*)d_in[8];   // (97,)
    float*       out   = (float*)d_out;           // (2048,97)

    cudaFuncSetAttribute(bilinear_kernel,
                         cudaFuncAttributeMaxDynamicSharedMemorySize, K5_SMEM_BYTES);

    build_ent_kernel<<<NENT, 192>>>(feats, pos);

    dim3 g2(NENT / 64, H_ / 128, 2);              // 8 x 6 x 2 = 96 blocks
    gemm_tanh_kernel<<<g2, 256>>>(Wh, bh, Wt, bt);

    init_out_kernel<<<(NROWS * L_ + 255) / 256, 256>>>(bc, out);

    l96_kernel<<<NROWS / 16, 128>>>(ht, Wc, out);

    bilinear_kernel<<<296, 384, K5_SMEM_BYTES>>>(ht, Wc, out);
}